// round 10
// baseline (speedup 1.0000x reference)
#include <cuda_runtime.h>
#include <cstdint>

// ---------------------------------------------------------------------------
// LightGCN forward: out = (x + A'x + A'(A'x)) / 3
// A'[col] = dis[col] * sum_in-edges dis[row] * v[row],  dis = rsqrt(indeg).
// N = 150000, D = 64 fp32, E = 2,000,000 ([2,E], int64 OR int32, runtime-
// detected). CSR (counting-sort by destination) -> atomic-free conv with
// register accumulation; feature dim in 4 quarter-passes (16 dims) so
// device-global scratch stays at ~19.4 MB (proven-safe size class).
// ---------------------------------------------------------------------------

#define MAXN 150016
#define MAXE 2000000
#define SCAN_B 1024
#define NBLK_MAX ((MAXN + SCAN_B - 1) / SCAN_B)
#define QW 16                 // floats per quarter pass

// Scratch: ~19.4 MB total.
__device__ int   g_shift;            // 1 if edge dtype int64, 0 if int32
__device__ int   g_degi[MAXN];       // in-degree (int)
__device__ int   g_cur[MAXN];        // excl offsets -> end offsets after sort
__device__ float g_dis[MAXN];
__device__ int   g_srow[MAXE];       // source row per edge, sorted by col, 8MB
__device__ float g_yq[(size_t)MAXN * QW];  // quarter-width emb1 slice, 9.6MB
__device__ int   g_bsum[NBLK_MAX];

// ---------------------------------------------------------------------------
__global__ void k_detect(const int2* __restrict__ p, int npairs) {
    __shared__ int nz;
    if (threadIdx.x == 0) nz = 0;
    __syncthreads();
    int local = 0;
    for (int i = threadIdx.x; i < npairs; i += blockDim.x)
        if (p[i].y != 0) local = 1;
    if (local) atomicOr(&nz, 1);
    __syncthreads();
    if (threadIdx.x == 0) g_shift = (nz == 0) ? 1 : 0;
}

__device__ __forceinline__ unsigned load_idx(const int* __restrict__ p32,
                                             long long pos, int shift) {
    return (unsigned)p32[pos << shift];
}

__global__ void k_zero_degi(int N) {
    int i = blockIdx.x * blockDim.x + threadIdx.x;
    if (i < N) g_degi[i] = 0;
}

__global__ void k_hist(const int* __restrict__ e32, int E, int N) {
    int i = blockIdx.x * blockDim.x + threadIdx.x;
    if (i >= E) return;
    int sh = g_shift;
    unsigned col = load_idx(e32, (long long)E + i, sh);
    if (col < (unsigned)N) atomicAdd(&g_degi[col], 1);
}

// Block-level exclusive scan of degi -> cur; per-block totals -> bsum.
__global__ void k_scan1(int N) {
    __shared__ int sh[SCAN_B];
    int tid = threadIdx.x;
    int gid = blockIdx.x * SCAN_B + tid;
    int v = (gid < N) ? g_degi[gid] : 0;
    sh[tid] = v;
    __syncthreads();
    for (int off = 1; off < SCAN_B; off <<= 1) {
        int t = (tid >= off) ? sh[tid - off] : 0;
        __syncthreads();
        sh[tid] += t;
        __syncthreads();
    }
    if (gid < N) g_cur[gid] = sh[tid] - v;  // exclusive within block
    if (tid == SCAN_B - 1) g_bsum[blockIdx.x] = sh[tid];
}

__global__ void k_scan2(int nb) {  // tiny serial scan of block sums
    if (threadIdx.x == 0) {
        int run = 0;
        for (int i = 0; i < nb; ++i) { int t = g_bsum[i]; g_bsum[i] = run; run += t; }
    }
}

__global__ void k_scan3(int N) {
    int gid = blockIdx.x * blockDim.x + threadIdx.x;
    if (gid < N) g_cur[gid] += g_bsum[gid / SCAN_B];
}

// Counting-sort scatter: place each edge's row under its destination col.
// Afterwards g_cur[col] == end offset; start = end - degi[col].
__global__ void k_sort(const int* __restrict__ e32, int E, int N) {
    int i = blockIdx.x * blockDim.x + threadIdx.x;
    if (i >= E) return;
    int sh = g_shift;
    unsigned row = load_idx(e32, i, sh);
    unsigned col = load_idx(e32, (long long)E + i, sh);
    if (row >= (unsigned)N || col >= (unsigned)N) return;
    int pos = atomicAdd(&g_cur[col], 1);
    g_srow[pos] = (int)row;
}

__global__ void k_dis(int N) {
    int i = blockIdx.x * blockDim.x + threadIdx.x;
    if (i >= N) return;
    int d = g_degi[i];
    g_dis[i] = (d > 0) ? rsqrtf((float)d) : 0.0f;
}

// conv1 (quarter q): y[node][0:16] = dis[node] * sum dis[row]*x[row][q*16+lane]
// 16 lanes per node (2 nodes per warp); gather = 64B coalesced per edge.
__global__ void k_csr1(const float* __restrict__ x, int N, int xoff) {
    int t = blockIdx.x * blockDim.x + threadIdx.x;
    int node = t >> 4;
    if (node >= N) return;
    int lane = t & 15;

    int end = g_cur[node];
    int deg = g_degi[node];
    int start = end - deg;

    float acc = 0.0f;
    for (int j = start; j < end; ++j) {
        int row = g_srow[j];
        float w = __ldg(&g_dis[row]);
        acc += w * __ldg(&x[(size_t)row * 64 + xoff + lane]);
    }
    g_yq[(size_t)node * QW + lane] = __ldg(&g_dis[node]) * acc;
}

// conv2 (quarter q), fused epilogue:
// out[node] = (x[node] + y[node] + dis[node]*sum dis[row]*y[row]) / 3
__global__ void k_csr2(const float* __restrict__ x, float* __restrict__ out,
                       int N, int xoff) {
    int t = blockIdx.x * blockDim.x + threadIdx.x;
    int node = t >> 4;
    if (node >= N) return;
    int lane = t & 15;

    int end = g_cur[node];
    int deg = g_degi[node];
    int start = end - deg;

    float acc = 0.0f;
    for (int j = start; j < end; ++j) {
        int row = g_srow[j];
        float w = __ldg(&g_dis[row]);
        acc += w * __ldg(&g_yq[(size_t)row * QW + lane]);
    }
    float dn = __ldg(&g_dis[node]);
    float yv = g_yq[(size_t)node * QW + lane];
    float xv = __ldg(&x[(size_t)node * 64 + xoff + lane]);
    out[(size_t)node * 64 + xoff + lane] = (xv + yv + dn * acc) * (1.0f / 3.0f);
}

// ---------------------------------------------------------------------------
extern "C" void kernel_launch(void* const* d_in, const int* in_sizes, int n_in,
                              void* d_out, int out_size) {
    // Input-order detection: x has N*64 = 9.6M elements; edge_index has
    // 2E = 4M elements. x is strictly larger.
    int ix = 0, ie = 1;
    if (n_in >= 2 && in_sizes[0] < in_sizes[1]) { ix = 1; ie = 0; }

    const float* x   = (const float*)d_in[ix];
    const int*   e32 = (const int*)d_in[ie];
    float*       out = (float*)d_out;

    int N = in_sizes[ix] / 64;
    int E = in_sizes[ie] / 2;
    if (N > MAXN) N = MAXN;
    if (E > MAXE) E = MAXE;

    const int TB = 256;
    const int gN  = (N + TB - 1) / TB;
    const int gE  = (E + TB - 1) / TB;
    const int nb  = (N + SCAN_B - 1) / SCAN_B;
    const long long workC = (long long)N * QW;
    const int gC  = (int)((workC + TB - 1) / TB);

    // dtype detect (reads <=8KB — in bounds under both interpretations)
    {
        int npairs = E;
        if (npairs > 1024) npairs = 1024;
        k_detect<<<1, 256>>>((const int2*)e32, npairs);
    }

    // CSR build: histogram -> scan -> sort
    k_zero_degi<<<gN, TB>>>(N);
    k_hist<<<gE, TB>>>(e32, E, N);
    k_scan1<<<nb, SCAN_B>>>(N);
    k_scan2<<<1, 32>>>(nb);
    k_scan3<<<gN, TB>>>(N);
    k_sort<<<gE, TB>>>(e32, E, N);
    k_dis<<<gN, TB>>>(N);

    // 4 quarter-passes over feature dim (16 dims each)
    for (int q = 0; q < 4; ++q) {
        int xoff = q * QW;
        k_csr1<<<gC, TB>>>(x, N, xoff);
        k_csr2<<<gC, TB>>>(x, out, N, xoff);
    }
}

// round 11
// speedup vs baseline: 1.1540x; 1.1540x over previous
#include <cuda_runtime.h>
#include <cuda_fp16.h>
#include <cstdint>

// ---------------------------------------------------------------------------
// LightGCN forward: out = (x + A'x + A'(A'x)) / 3
// per-edge norm (row->col): dis[row]*dis[col], dis = rsqrt(indeg) or 0.
// N = 150000, D = 64 fp32, E = 2,000,000 ([2,E], int64 OR int32, runtime-
// detected). Single full-width pass: y accumulated in fp32 directly in d_out,
// then copied once to an fp16 buffer (19.2 MB) for conv2's gather. Device-
// global scratch ~20.4 MB (proven-safe size class; 39.6 MB fails the harness
// mem check). Atomic v4-REDG scatter (round 10 showed CSR is slower: the
// kernel is issue-bound per edge, and no-return reductions are ~free).
// ---------------------------------------------------------------------------

#define MAXN 150016

// Scratch: ~20.4 MB total.
__device__ int     g_shift;              // 1 if edge dtype int64, 0 if int32
__device__ float   g_deg[MAXN];
__device__ float   g_dis[MAXN];
__device__ __half2 g_yh[MAXN * 32];      // fp16 copy of y = A'x, 19.2 MB

// ---------------------------------------------------------------------------
// Detect edge dtype: int64 node ids (<2^31) have zero high words; int32 pairs
// have a random nonzero second component almost surely.
__global__ void k_detect(const int2* __restrict__ p, int npairs) {
    __shared__ int nz;
    if (threadIdx.x == 0) nz = 0;
    __syncthreads();
    int local = 0;
    for (int i = threadIdx.x; i < npairs; i += blockDim.x)
        if (p[i].y != 0) local = 1;
    if (local) atomicOr(&nz, 1);
    __syncthreads();
    if (threadIdx.x == 0) g_shift = (nz == 0) ? 1 : 0;
}

__device__ __forceinline__ unsigned load_idx(const int* __restrict__ p32,
                                             long long pos, int shift) {
    return (unsigned)p32[pos << shift];
}

__global__ void k_zero_deg(int N) {
    int i = blockIdx.x * blockDim.x + threadIdx.x;
    if (i < N) g_deg[i] = 0.0f;
}

__global__ void k_deg(const int* __restrict__ e32, int E, int N) {
    int i = blockIdx.x * blockDim.x + threadIdx.x;
    if (i >= E) return;
    int sh = g_shift;
    unsigned col = load_idx(e32, (long long)E + i, sh);
    if (col < (unsigned)N) atomicAdd(&g_deg[col], 1.0f);
}

__global__ void k_dis(int N) {
    int i = blockIdx.x * blockDim.x + threadIdx.x;
    if (i >= N) return;
    float d = g_deg[i];
    g_dis[i] = (d > 0.0f) ? rsqrtf(d) : 0.0f;
}

__global__ void k_zero_out(float4* __restrict__ out, int n4) {
    int i = blockIdx.x * blockDim.x + threadIdx.x;
    if (i < n4) out[i] = make_float4(0.f, 0.f, 0.f, 0.f);
}

// conv1: out[col] += x[row] * nr, full 64 dims. 16 lanes/edge, one float4
// each: 256B coalesced gather + 256B v4-REDG scatter. Index/dis loads are
// 16-lane broadcasts (one transaction each).
__global__ void __launch_bounds__(256) k_conv1(
        const float4* __restrict__ x, float4* __restrict__ out,
        const int* __restrict__ e32, int E, int N) {
    long long t = (long long)blockIdx.x * blockDim.x + threadIdx.x;
    long long e = t >> 4;
    if (e >= E) return;
    int c = (int)(t & 15);

    int sh = g_shift;
    unsigned row = load_idx(e32, e, sh);
    unsigned col = load_idx(e32, (long long)E + e, sh);
    if (row >= (unsigned)N || col >= (unsigned)N) return;

    float nr = __ldg(&g_dis[row]) * __ldg(&g_dis[col]);
    float4 v = __ldg(&x[(size_t)row * 16 + c]);
    v.x *= nr; v.y *= nr; v.z *= nr; v.w *= nr;

    float4* pd = &out[(size_t)col * 16 + c];
    asm volatile("red.global.add.v4.f32 [%0], {%1, %2, %3, %4};"
                 :: "l"(pd), "f"(v.x), "f"(v.y), "f"(v.z), "f"(v.w)
                 : "memory");
}

// mid (fused): read y from out, write fp16 copy for conv2's gather, and
// rewrite out = (x + y) / 3. One pass over all three buffers.
__global__ void k_mid(const float4* __restrict__ x, float4* __restrict__ out,
                      int n4) {
    int i = blockIdx.x * blockDim.x + threadIdx.x;
    if (i >= n4) return;
    float4 y = out[i];

    uint2 h;
    __half2 h0 = __floats2half2_rn(y.x, y.y);
    __half2 h1 = __floats2half2_rn(y.z, y.w);
    h.x = *(const unsigned*)&h0;
    h.y = *(const unsigned*)&h1;
    ((uint2*)g_yh)[i] = h;

    float4 a = __ldg(&x[i]);
    const float s = 1.0f / 3.0f;
    out[i] = make_float4((a.x + y.x) * s, (a.y + y.y) * s,
                         (a.z + y.z) * s, (a.w + y.w) * s);
}

// conv2: out[col] += y_h[row] * nr / 3.  16 lanes/edge: 8B fp16x4 gather
// (128B/edge) + 16B v4-REDG scatter (256B/edge).
__global__ void __launch_bounds__(256) k_conv2(
        float4* __restrict__ out, const int* __restrict__ e32, int E, int N) {
    long long t = (long long)blockIdx.x * blockDim.x + threadIdx.x;
    long long e = t >> 4;
    if (e >= E) return;
    int c = (int)(t & 15);

    int sh = g_shift;
    unsigned row = load_idx(e32, e, sh);
    unsigned col = load_idx(e32, (long long)E + e, sh);
    if (row >= (unsigned)N || col >= (unsigned)N) return;

    float nr = __ldg(&g_dis[row]) * __ldg(&g_dis[col]) * (1.0f / 3.0f);

    uint2 h = __ldg(&((const uint2*)g_yh)[(size_t)row * 16 + c]);
    float2 f0 = __half22float2(*(const __half2*)&h.x);
    float2 f1 = __half22float2(*(const __half2*)&h.y);
    float4 v = make_float4(f0.x * nr, f0.y * nr, f1.x * nr, f1.y * nr);

    float4* pd = &out[(size_t)col * 16 + c];
    asm volatile("red.global.add.v4.f32 [%0], {%1, %2, %3, %4};"
                 :: "l"(pd), "f"(v.x), "f"(v.y), "f"(v.z), "f"(v.w)
                 : "memory");
}

// ---------------------------------------------------------------------------
extern "C" void kernel_launch(void* const* d_in, const int* in_sizes, int n_in,
                              void* d_out, int out_size) {
    // Input-order detection: x has N*64 = 9.6M elements; edge_index has
    // 2E = 4M elements. x is strictly larger.
    int ix = 0, ie = 1;
    if (n_in >= 2 && in_sizes[0] < in_sizes[1]) { ix = 1; ie = 0; }

    const float4* x   = (const float4*)d_in[ix];
    const int*    e32 = (const int*)d_in[ie];
    float4*       out = (float4*)d_out;

    int N = in_sizes[ix] / 64;
    int E = in_sizes[ie] / 2;
    if (N > MAXN) N = MAXN;

    const int TB = 256;
    const int n4 = N * 16;
    const int gO = (n4 + TB - 1) / TB;
    const int gN = (N + TB - 1) / TB;
    const int gE1 = (E + TB - 1) / TB;
    const long long workE = (long long)E * 16;
    const int gE16 = (int)((workE + TB - 1) / TB);

    // dtype detect (reads <=8KB — in bounds under both interpretations)
    {
        int npairs = E;
        if (npairs > 1024) npairs = 1024;
        k_detect<<<1, 256>>>((const int2*)e32, npairs);
    }

    // degrees + normalization coefficients
    k_zero_deg<<<gN, TB>>>(N);
    k_deg<<<gE1, TB>>>(e32, E, N);
    k_dis<<<gN, TB>>>(N);

    // y = A'x accumulated in fp32 directly in out
    k_zero_out<<<gO, TB>>>(out, n4);
    k_conv1<<<gE16, TB>>>(x, out, e32, E, N);

    // fp16 copy of y for conv2's gather; out = (x + y) / 3
    k_mid<<<gO, TB>>>(x, out, n4);

    // out += A'(y) / 3
    k_conv2<<<gE16, TB>>>(out, e32, E, N);
}